// round 11
// baseline (speedup 1.0000x reference)
#include <cuda_runtime.h>
#include <cuda.h>
#include <dlfcn.h>
#include <cstdint>
#include <cstddef>

// ============================================================================
// MaskedLinear: y = x @ (W*mask)^T + b ; M=8192, K=4096, N=4096 fp32.
//
// gemm   : PERSISTENT cg2 tcgen05 kind::tf32 SS GEMM, pair tile 256x512,
//          BK=32, 4-stage ring fed by cta_group::2 TMA.
//          FUSED PREP: epilogue warps (idle during mainloop) fold
//          g_wm = rn_tf32(W*mask); per-512-row-block readiness counters
//          (g_wrdy, release/acquire) gate the producers' B-tile TMAs.
//          74 pairs x 3 full tiles (0..221); remainder tiles 222..255 SPLIT-K:
//          owner pair s (<34): K[0:2048) -> out (+bias);
//          helper pair 34+s   : K[2048:4096) -> g_part (raw).
// reduce : out += g_part over the 34 split tiles; resets g_wrdy for replay.
// Fallback (non-103a PTX pass; never selected on GB300): mma.sync tf32 with
//          inline redundant prep.
// ============================================================================

#define SWZ(o) ((o) ^ (((o) >> 3) & 0x70))

static constexpr int BK = 32;                 // floats per K-chunk (128 B)
static constexpr int THREADS = 288;           // warps 0-7 prep+epilogue, warp 8 ctrl
static constexpr int STAGES = 4;

static constexpr int A_BYTES  = 128 * 128;    // 16 KB
static constexpr int B0_BYTES = 128 * 128;
static constexpr int B1_BYTES = 128 * 128;
static constexpr int STAGE_BYTES = A_BYTES + B0_BYTES + B1_BYTES;     // 48 KB
static constexpr int SMEM_STAGE0 = 1024;
static constexpr int SMEM_TOTAL = SMEM_STAGE0 + STAGES * STAGE_BYTES; // 197632
static constexpr int TMEM_COLS = 512;
static constexpr uint32_t STAGE_TX = (uint32_t)STAGE_BYTES * 2;       // both CTAs

static constexpr int NCTAS = 148;             // persistent grid size

// idesc kind::tf32 cg2: dfmt=F32(1)<<4, atype=TF32(2)<<7, btype=TF32(2)<<10,
// N=256 -> 32<<17, M=256 -> 16<<24.
static constexpr uint32_t IDESC =
    (1u << 4) | (2u << 7) | (2u << 10) | (32u << 17) | (16u << 24);

// SW128 K-major smem descriptor: layout=SW128(2), version=1, SBO=64, LBO=1
static constexpr uint64_t DESC_BASE =
    (2ULL << 61) | (1ULL << 46) | (64ULL << 32) | (1ULL << 16);

// mbar offsets
#define FULL_OFF(s)  (16u + (uint32_t)(s) * 8u)    // leader, tx-based
#define DONE_OFF(s)  (48u + (uint32_t)(s) * 8u)    // both CTAs, count 1
#define MMAD_OFF(p)  (88u + (uint32_t)(p) * 8u)    // both CTAs, count 1
#define EPI_OFF(p)   (104u + (uint32_t)(p) * 8u)   // leader, count 16

// --- fallback layout (base sm_103 pass only; never runs on GB300) ---
static constexpr int FB_A_BYTES = 128 * 128;
static constexpr int FB_B_BYTES = 256 * 128;
static constexpr int FB_STAGE_BYTES = FB_A_BYTES + FB_B_BYTES;   // 49152
static constexpr int NLOAD = 256;

static constexpr int NSPLIT = 34;              // split tiles 222..255

__device__ float g_wm[4096ull * 4096ull];      // 64 MiB scratch
__device__ float g_part[(size_t)NSPLIT * 256 * 512];   // split-K partials
__device__ int   g_wrdy[8];                    // per-512-row W-block ready count

// ---------------------------------------------------------------------------
// portable helpers
// ---------------------------------------------------------------------------
__device__ __forceinline__ uint32_t smem_u32(const void* p) {
    uint32_t a;
    asm("{ .reg .u64 t; cvta.to.shared.u64 t, %1; cvt.u32.u64 %0, t; }"
        : "=r"(a) : "l"(p));
    return a;
}

__device__ __forceinline__ float to_tf32_rn(float x) {
    uint32_t u;
    asm("cvt.rna.tf32.f32 %0, %1;" : "=r"(u) : "f"(x));
    return __uint_as_float(u);
}

__device__ __forceinline__ void cp16(uint32_t s, const float* g) {
    asm volatile("cp.async.cg.shared.global [%0], [%1], 16;"
                 :: "r"(s), "l"(__cvta_generic_to_global((const void*)g)));
}

__device__ __forceinline__ uint32_t lds_u32(uint32_t addr) {
    uint32_t v;
    asm volatile("ld.shared.b32 %0, [%1];" : "=r"(v) : "r"(addr));
    return v;
}

#define CLUSTER_SYNC() do {                                          \
    asm volatile("barrier.cluster.arrive.aligned;" ::: "memory");    \
    asm volatile("barrier.cluster.wait.aligned;" ::: "memory");      \
} while (0)

// ---------------------------------------------------------------------------
// sm_103a-only pieces
// ---------------------------------------------------------------------------
#if defined(__CUDA_ARCH_FEAT_SM103_ALL) || defined(__CUDA_ARCH_FEAT_SM100_ALL) || !defined(__CUDA_ARCH__)

__device__ __forceinline__ uint32_t elect_one() {
    uint32_t p;
    asm volatile(
        "{\n\t.reg .pred p;\n\telect.sync _|p, 0xFFFFFFFF;\n\t"
        "selp.b32 %0, 1, 0, p;\n\t}" : "=r"(p));
    return p;
}

__device__ __forceinline__ void mma_tf32_cg2(uint32_t d_tmem, uint64_t a_desc,
                                             uint64_t b_desc, uint32_t en) {
#if defined(__CUDA_ARCH__)
    asm volatile(
        "{\n\t.reg .pred p;\n\tsetp.ne.u32 p, %6, 0;\n\t"
        "tcgen05.mma.cta_group::2.kind::tf32 [%0], %1, %2, %3, "
        "{%4, %4, %4, %4, %4, %4, %4, %4}, p;\n\t}"
        :: "r"(d_tmem), "l"(a_desc), "l"(b_desc), "r"(IDESC),
           "r"(0u), "r"(0u), "r"(en)
        : "memory");
#endif
}

__device__ __forceinline__ void tma_cg2(uint32_t dst, const void* map,
                                        int cx, int cy, uint32_t mbar) {
#if defined(__CUDA_ARCH__)
    asm volatile(
        "{\n\t.reg .b32 lb;\n\t.reg .b32 cz;\n\tmov.b32 cz, 0;\n\t"
        "and.b32 lb, %4, 0xFEFFFFFF;\n\t"
        "cp.async.bulk.tensor.3d.cta_group::2.shared::cluster.global"
        ".tile.mbarrier::complete_tx::bytes [%0], [%1, {%2, %3, cz}], [lb];\n\t}"
        :: "r"(dst), "l"(map), "r"(cx), "r"(cy), "r"(mbar)
        : "memory");
#endif
}

#define MBARRIER_INIT(addr, cnt) \
    asm volatile("mbarrier.init.shared.b64 [%0], %1;" :: "r"(addr), "r"(cnt) : "memory")

#define MBARRIER_EXPECT_TX(addr, bytes) \
    asm volatile("mbarrier.arrive.expect_tx.shared.b64 _, [%0], %1;" \
        :: "r"((uint32_t)(addr)), "r"((uint32_t)(bytes)) : "memory")

#define MBARRIER_WAIT_PARITY(addr, ph) do {                                   \
    uint32_t _m = (uint32_t)(addr); uint32_t _p = (uint32_t)(ph);             \
    uint32_t _d;                                                              \
    asm volatile("{\n\t.reg .pred p;\n\t"                                     \
        "mbarrier.try_wait.parity.acquire.cta.shared::cta.b64 p, [%1], %2;\n\t" \
        "selp.b32 %0, 1, 0, p;\n\t}" : "=r"(_d) : "r"(_m), "r"(_p) : "memory"); \
    if (!_d) {                                                                \
        asm volatile("{\n\t.reg .pred P1;\n\t"                                \
            "WL_%=:\n\t"                                                      \
            "mbarrier.try_wait.parity.acquire.cta.shared::cta.b64 P1, [%0], %1, 0x989680;\n\t" \
            "@P1 bra.uni WD_%=;\n\t"                                          \
            "bra.uni WL_%=;\n\t"                                              \
            "WD_%=:\n\t}" :: "r"(_m), "r"(_p) : "memory");                    \
    }                                                                         \
} while (0)

#define MBARRIER_ARRIVE_LOCAL(addr)                                           \
    asm volatile("mbarrier.arrive.shared.b64 _, [%0];"                        \
        :: "r"((uint32_t)(addr)) : "memory")

#define MBARRIER_ARRIVE_RANK0(addr)                                           \
    asm volatile("{\n\t.reg .b32 r;\n\t"                                      \
        "mapa.shared::cluster.u32 r, %0, 0;\n\t"                              \
        "mbarrier.arrive.shared::cluster.b64 _, [r];\n\t}"                    \
        :: "r"((uint32_t)(addr)) : "memory")

#define TCGEN05_COMMIT_MC_CG2(addr, mask)                                     \
    asm volatile("tcgen05.commit.cta_group::2.mbarrier::arrive::one.shared::cluster.multicast::cluster.b64 [%0], %1;" \
        :: "r"((uint32_t)(addr)), "h"((uint16_t)(mask)) : "memory")

#define LDTM_X16(r, addr)                                                     \
    asm volatile("tcgen05.ld.sync.aligned.32x32b.x16.b32 "                    \
        "{%0, %1, %2, %3, %4, %5, %6, %7, "                                   \
        " %8, %9, %10, %11, %12, %13, %14, %15}, [%16];"                      \
        : "=r"((r)[0]),  "=r"((r)[1]),  "=r"((r)[2]),  "=r"((r)[3]),          \
          "=r"((r)[4]),  "=r"((r)[5]),  "=r"((r)[6]),  "=r"((r)[7]),          \
          "=r"((r)[8]),  "=r"((r)[9]),  "=r"((r)[10]), "=r"((r)[11]),         \
          "=r"((r)[12]), "=r"((r)[13]), "=r"((r)[14]), "=r"((r)[15])          \
        : "r"(addr))

// spin until W-block n is fully prepped (148 CTA arrivals), then proxy-fence
__device__ __forceinline__ void wait_wrdy(int n) {
#if defined(__CUDA_ARCH__)
    int v;
    do {
        asm volatile("ld.acquire.gpu.global.b32 %0, [%1];"
                     : "=r"(v) : "l"(g_wrdy + n) : "memory");
        if (v < NCTAS) __nanosleep(128);
    } while (v < NCTAS);
    asm volatile("fence.proxy.async.global;" ::: "memory");
#endif
}

// chunk c -> tile/k mapping and TMA issue; waits W-block readiness on ni change
__device__ __forceinline__ void issue_tma_chunk(
    int c, int n3c, int pair, int NPAIRS, int t4, int k4,
    uint32_t sa, const CUtensorMap* tmx, const CUtensorMap* tmw,
    uint32_t mbar, int rank, int* last_ni)
{
#if defined(__CUDA_ARCH__)
    int t, k;
    if (c < n3c) { t = pair + (c >> 7) * NPAIRS; k = c & 127; }
    else         { t = t4; k = k4 + (c - n3c); }
    const int mi = t & 31, ni = t >> 5;            // NT_M = 32
    if (ni != *last_ni) { wait_wrdy(ni); *last_ni = ni; }
    tma_cg2(sa,                      tmx, k * 32, mi * 256 + rank * 128, mbar);
    tma_cg2(sa + A_BYTES,            tmw, k * 32, ni * 512 + rank * 128, mbar);
    tma_cg2(sa + A_BYTES + B0_BYTES, tmw, k * 32, ni * 512 + 256 + rank * 128, mbar);
#endif
}

#endif // sm_103a-only pieces

// ---------------------------------------------------------------------------
// reduce kernel: out += g_part over the 34 split tiles; reset g_wrdy
// ---------------------------------------------------------------------------
__global__ void reduce_kernel(float* __restrict__ out, int N) {
    const int total4 = NSPLIT * 256 * 512 / 4;        // 1,114,112
    int i = blockIdx.x * blockDim.x + threadIdx.x;
    if (blockIdx.x == 0 && threadIdx.x < 8) g_wrdy[threadIdx.x] = 0;
    if (i >= total4) return;
    const int e = i * 4;
    const int s = e / (256 * 512);
    const int rem = e % (256 * 512);
    const int row = rem >> 9, col = rem & 511;
    const int t = 222 + s;
    const int mi = t & 31, ni = t >> 5;
    float4 p = reinterpret_cast<const float4*>(g_part)[i];
    float4* op = reinterpret_cast<float4*>(
        out + (size_t)(mi * 256 + row) * N + ni * 512 + col);
    float4 v = *op;
    v.x += p.x; v.y += p.y; v.z += p.z; v.w += p.w;
    *op = v;
}

// ---------------------------------------------------------------------------
// fallback stage load (base pass only)
// ---------------------------------------------------------------------------
__device__ __forceinline__ void load_stage_fb(uint32_t sb, int buf,
                                              const float* gA, const float* gB,
                                              int K, int ltid) {
    const uint32_t sa  = sb + SMEM_STAGE0 + buf * FB_STAGE_BYTES;
    const uint32_t sbm = sa + FB_A_BYTES;
#pragma unroll
    for (int i = 0; i < 4; i++) {
        int u = ltid + i * NLOAD;
        int row = u >> 3, seg = u & 7;
        uint32_t off = (uint32_t)(row * 128 + seg * 16);
        cp16(sa + SWZ(off), gA + (size_t)row * K + seg * 4);
    }
#pragma unroll
    for (int i = 0; i < 8; i++) {
        int u = ltid + i * NLOAD;
        int row = u >> 3, seg = u & 7;
        uint32_t off = (uint32_t)(row * 128 + seg * 16);
        cp16(sbm + SWZ(off), gB + (size_t)row * K + seg * 4);
    }
    asm volatile("cp.async.commit_group;" ::: "memory");
}

// ---------------------------------------------------------------------------
// main GEMM kernel — persistent, TMA-fed cg2, fused W-prep, split-K
// ---------------------------------------------------------------------------
__global__ void __launch_bounds__(THREADS, 1) __cluster_dims__(2, 1, 1)
masked_gemm_kernel(const float* __restrict__ x, const float* __restrict__ w,
                   const float* __restrict__ maskp,
                   const float* __restrict__ bias,
                   float* __restrict__ out, int M, int N, int K,
                   const __grid_constant__ CUtensorMap tmx,
                   const __grid_constant__ CUtensorMap tmw) {
    extern __shared__ char smem[];
    const uint32_t sb = smem_u32(smem);
    const int tid = threadIdx.x;
    const int wid = tid >> 5;
    const int lid = tid & 31;
    const int rank = blockIdx.x & 1;
    const int pair = blockIdx.x >> 1;
    const int NPAIRS = (int)(gridDim.x >> 1);          // 74

#if defined(__CUDA_ARCH_FEAT_SM103_ALL) || defined(__CUDA_ARCH_FEAT_SM100_ALL)
    // ======================== persistent TMA+cg2 path ======================
    const bool has4   = (pair < 2 * NSPLIT);           // pairs 0..67
    const int  s34    = (pair < NSPLIT) ? pair : pair - NSPLIT;
    const int  t4     = 222 + s34;
    const int  k4     = (pair < NSPLIT) ? 0 : 64;      // owner K-lo / helper K-hi
    const int  n3c    = 3 * 128;
    const int  tot    = n3c + (has4 ? 64 : 0);
    const int  n_items = has4 ? 4 : 3;

    if (wid == 8) {
        asm volatile("tcgen05.alloc.cta_group::2.sync.aligned.shared::cta.b32 [%0], %1;"
                     :: "r"(sb), "r"((uint32_t)TMEM_COLS) : "memory");
        asm volatile("tcgen05.relinquish_alloc_permit.cta_group::2.sync.aligned;");
    }
    if (tid == 0) {
#pragma unroll
        for (int s = 0; s < STAGES; s++) {
            MBARRIER_INIT(sb + FULL_OFF(s), 1);
            MBARRIER_INIT(sb + DONE_OFF(s), 1);
        }
        MBARRIER_INIT(sb + MMAD_OFF(0), 1);
        MBARRIER_INIT(sb + MMAD_OFF(1), 1);
        MBARRIER_INIT(sb + EPI_OFF(0), 16);
        MBARRIER_INIT(sb + EPI_OFF(1), 16);
    }
    __syncthreads();
    uint32_t tmem;
    asm volatile("ld.shared.b32 %0, [%1];" : "=r"(tmem) : "r"(sb));
    CLUSTER_SYNC();

    if (wid == 8) {
        if (elect_one()) {
            int last_ni = -1;
            if (rank == 0) {
                uint64_t AD[STAGES], B0D[STAGES], B1D[STAGES];
#pragma unroll
                for (int s = 0; s < STAGES; s++) {
                    const uint32_t sa = sb + SMEM_STAGE0 + s * STAGE_BYTES;
                    AD[s]  = DESC_BASE | ((sa >> 4) & 0x3FFF);
                    B0D[s] = DESC_BASE | (((sa + A_BYTES) >> 4) & 0x3FFF);
                    B1D[s] = DESC_BASE | (((sa + A_BYTES + B0_BYTES) >> 4) & 0x3FFF);
                }
                for (int c = 0; c < 3; c++) {
                    const uint32_t sa = sb + SMEM_STAGE0 + (c & 3) * STAGE_BYTES;
                    MBARRIER_EXPECT_TX(sb + FULL_OFF(c & 3), STAGE_TX);
                    issue_tma_chunk(c, n3c, pair, NPAIRS, t4, k4, sa,
                                    &tmx, &tmw, sb + FULL_OFF(c & 3), rank, &last_ni);
                }
                for (int c = 0; c < tot; c++) {
                    const int s = c & 3;
                    const int it = c >> 7;
                    MBARRIER_WAIT_PARITY(sb + FULL_OFF(s), (c >> 2) & 1);
                    if ((c & 127) == 0 && it >= 1) {
                        const int pt = it - 1;
                        MBARRIER_WAIT_PARITY(sb + EPI_OFF(pt & 1), (pt >> 1) & 1);
                    }
                    const uint64_t ad = AD[s], b0d = B0D[s], b1d = B1D[s];
                    const uint32_t nf = (uint32_t)((c & 127) != 0);
#pragma unroll
                    for (int ks = 0; ks < 4; ks++) {
                        uint32_t e = nf | (uint32_t)(ks > 0);
                        mma_tf32_cg2(tmem,        ad + ks * 2, b0d + ks * 2, e);
                        mma_tf32_cg2(tmem + 256u, ad + ks * 2, b1d + ks * 2, e);
                    }
                    TCGEN05_COMMIT_MC_CG2(sb + DONE_OFF(s), 0x3);
                    if (((c & 127) == 127) || (c == tot - 1)) {
                        TCGEN05_COMMIT_MC_CG2(sb + MMAD_OFF(it & 1), 0x3);
                    }
                    if (c >= 1) {
                        MBARRIER_WAIT_PARITY(sb + DONE_OFF((c - 1) & 3),
                                             ((c - 1) >> 2) & 1);
                    }
                    const int cn = c + 3;
                    if (cn < tot) {
                        const uint32_t sn = sb + SMEM_STAGE0 + (cn & 3) * STAGE_BYTES;
                        MBARRIER_EXPECT_TX(sb + FULL_OFF(cn & 3), STAGE_TX);
                        issue_tma_chunk(cn, n3c, pair, NPAIRS, t4, k4, sn,
                                        &tmx, &tmw, sb + FULL_OFF(cn & 3), rank, &last_ni);
                    }
                }
            } else {
                for (int c = 0; c < tot; c++) {
                    if (c >= STAGES) {
                        MBARRIER_WAIT_PARITY(sb + DONE_OFF((c - 4) & 3),
                                             ((c - 4) >> 2) & 1);
                    }
                    const uint32_t sa = sb + SMEM_STAGE0 + (c & 3) * STAGE_BYTES;
                    issue_tma_chunk(c, n3c, pair, NPAIRS, t4, k4, sa,
                                    &tmx, &tmw, sb + FULL_OFF(c & 3), rank, &last_ni);
                }
            }
        }
    } else {
        // ---------------- prep warps: fold W*mask -> g_wm ------------------
        // CTA b preps rows b + 148j (j ascending). After finishing all its
        // rows inside a 512-row block: bar -> proxy fence -> release-inc.
        {
            int blk_prev = 0;                          // first row < 148 -> blk 0
            for (int j = 0; j < 28; j++) {
                const int row = (int)blockIdx.x + NCTAS * j;
                if (row < 4096) {
                    const float4* wr = reinterpret_cast<const float4*>(
                        w + (size_t)row * 4096);
                    const float4* mr = reinterpret_cast<const float4*>(
                        maskp + (size_t)row * 4096);
                    float4* dr = reinterpret_cast<float4*>(
                        g_wm + (size_t)row * 4096);
                    for (int q = tid; q < 1024; q += 256) {
                        float4 a = wr[q], b = mr[q], r;
                        r.x = to_tf32_rn(a.x * b.x);
                        r.y = to_tf32_rn(a.y * b.y);
                        r.z = to_tf32_rn(a.z * b.z);
                        r.w = to_tf32_rn(a.w * b.w);
                        dr[q] = r;
                    }
                }
                const int nrow = (int)blockIdx.x + NCTAS * (j + 1);
                const int blk_next = (nrow < 4096) ? (nrow >> 9) : 8;
                if (blk_next != blk_prev) {
                    asm volatile("bar.sync 1, 256;" ::: "memory");
                    if (tid == 0) {
                        asm volatile("fence.proxy.async.global;" ::: "memory");
                        for (int n = blk_prev; n < blk_next; n++) {
                            asm volatile(
                                "red.release.gpu.global.add.s32 [%0], 1;"
                                :: "l"(g_wrdy + n) : "memory");
                        }
                    }
                    blk_prev = blk_next;
                }
            }
        }

        // ------ epilogue: UNIFORM body, single LDTM.x16 per wait -----------
        const int sub = wid & 3;
        const int half = wid >> 2;
        const int prow = rank * 128 + sub * 32 + lid;
        for (int it = 0; it < n_items; it++) {
            MBARRIER_WAIT_PARITY(sb + MMAD_OFF(it & 1), (it >> 1) & 1);
            asm volatile("tcgen05.fence::after_thread_sync;" ::: "memory");
            const int t = (it < 3) ? (pair + it * NPAIRS) : t4;
            const int mi = t & 31, ni = t >> 5;
            const bool is_helper = (it == 3) && (pair >= NSPLIT);

            float* orow;
            float bw;
            if (is_helper) {
                orow = g_part + ((size_t)s34 * 256 + prow) * 512;
                bw = 0.0f;
            } else {
                orow = out + (size_t)(mi * 256 + prow) * N + ni * 512;
                bw = 1.0f;
            }
            const float* brow = bias + ni * 512;

#pragma unroll
            for (int cc = 0; cc < 256; cc += 16) {
                const int col = half * 256 + cc;
                uint32_t r[16];
                LDTM_X16(r, tmem + (uint32_t)col);
                asm volatile("tcgen05.wait::ld.sync.aligned;" ::: "memory");
                const float4* bp = reinterpret_cast<const float4*>(brow + col);
                float4* op = reinterpret_cast<float4*>(orow + col);
#pragma unroll
                for (int j = 0; j < 4; j++) {
                    float4 bv = bp[j];
                    float4 v;
                    v.x = __uint_as_float(r[4 * j + 0]) + bw * bv.x;
                    v.y = __uint_as_float(r[4 * j + 1]) + bw * bv.y;
                    v.z = __uint_as_float(r[4 * j + 2]) + bw * bv.z;
                    v.w = __uint_as_float(r[4 * j + 3]) + bw * bv.w;
                    op[j] = v;
                }
            }
            asm volatile("tcgen05.fence::before_thread_sync;" ::: "memory");
            if (elect_one()) {
                if (rank == 0) MBARRIER_ARRIVE_LOCAL(sb + EPI_OFF(it & 1));
                else           MBARRIER_ARRIVE_RANK0(sb + EPI_OFF(it & 1));
            }
        }
    }

    __syncthreads();
    CLUSTER_SYNC();
    if (wid == 8) {
        asm volatile("tcgen05.dealloc.cta_group::2.sync.aligned.b32 %0, %1;"
                     :: "r"(tmem), "r"((uint32_t)TMEM_COLS));
    }
    CLUSTER_SYNC();

#else
    // ======================= mma.sync tf32 fallback ========================
    // Full-K over all 256 tiles; inline redundant prep of each tile's W rows.
    for (int i = blockIdx.x * blockDim.x + threadIdx.x;
         i < NSPLIT * 256 * 512 / 4; i += gridDim.x * blockDim.x) {
        reinterpret_cast<float4*>(g_part)[i] = make_float4(0.f, 0.f, 0.f, 0.f);
    }
    const int wm = (wid & 1) * 64;
    const int wn = ((wid >> 1) & 3) * 64;
    const int g  = lid >> 2;
    const int t4l = lid & 3;
    const int KCH = K / BK;

    for (int t = pair; t < 256; t += NPAIRS) {
        const int mi = t & 31, ni = t >> 5;
        const int m0 = mi * 256 + rank * 128;
        const int n0b = ni * 512;
        const float* gA0 = x + (size_t)m0 * K;

        // redundant prep of this tile's 512 W rows (same-value races benign)
        {
            const size_t base4 = (size_t)n0b * K / 4;
            for (int q = tid; q < 512 * K / 4; q += THREADS) {
                float4 a = reinterpret_cast<const float4*>(w)[base4 + q];
                float4 b = reinterpret_cast<const float4*>(maskp)[base4 + q];
                float4 r;
                r.x = to_tf32_rn(a.x * b.x);
                r.y = to_tf32_rn(a.y * b.y);
                r.z = to_tf32_rn(a.z * b.z);
                r.w = to_tf32_rn(a.w * b.w);
                reinterpret_cast<float4*>(g_wm)[base4 + q] = r;
            }
        }
        __syncthreads();

        for (int h = 0; h < 2; h++) {
            const float* gB0 = g_wm + (size_t)(n0b + h * 256) * K;

            float acc[4][8][4];
#pragma unroll
            for (int i = 0; i < 4; i++)
#pragma unroll
                for (int j = 0; j < 8; j++)
#pragma unroll
                    for (int c = 0; c < 4; c++) acc[i][j][c] = 0.0f;

            if (tid < NLOAD) {
#pragma unroll
                for (int s = 0; s < 3; s++)
                    load_stage_fb(sb, s, gA0 + s * BK, gB0 + s * BK, K, tid);
            }

            for (int k = 0; k < KCH; k++) {
                if (tid < NLOAD) {
                    int pend = KCH - 1 - k; if (pend > 2) pend = 2;
                    if (pend <= 0)      asm volatile("cp.async.wait_group 0;" ::: "memory");
                    else if (pend == 1) asm volatile("cp.async.wait_group 1;" ::: "memory");
                    else                asm volatile("cp.async.wait_group 2;" ::: "memory");
                }
                __syncthreads();

                if (tid < NLOAD && k + 3 < KCH) {
                    const int c = k + 3;
                    load_stage_fb(sb, (k + 3) & 3, gA0 + (size_t)c * BK,
                                  gB0 + (size_t)c * BK, K, tid);
                }

                if (wid < 8) {
                    const uint32_t sa = sb + SMEM_STAGE0 + (k & 3) * FB_STAGE_BYTES;
                    const uint32_t sB = sa + FB_A_BYTES;
#pragma unroll
                    for (int k8 = 0; k8 < 4; k8++) {
                        const int kc = k8 * 8;
                        uint32_t a[4][4];
#pragma unroll
                        for (int mt = 0; mt < 4; mt++) {
                            const int r0 = wm + mt * 16 + g;
                            const int c0 = kc + t4l;
                            a[mt][0] = lds_u32(sa + SWZ((uint32_t)(r0 * 128 + c0 * 4)));
                            a[mt][1] = lds_u32(sa + SWZ((uint32_t)((r0 + 8) * 128 + c0 * 4)));
                            a[mt][2] = lds_u32(sa + SWZ((uint32_t)(r0 * 128 + (c0 + 4) * 4)));
                            a[mt][3] = lds_u32(sa + SWZ((uint32_t)((r0 + 8) * 128 + (c0 + 4) * 4)));
                        }
                        uint32_t b[8][2];
#pragma unroll
                        for (int nt = 0; nt < 8; nt++) {
                            const int n = wn + nt * 8 + g;
                            const int ck = kc + t4l;
                            b[nt][0] = lds_u32(sB + SWZ((uint32_t)(n * 128 + ck * 4)));
                            b[nt][1] = lds_u32(sB + SWZ((uint32_t)(n * 128 + (ck + 4) * 4)));
                        }
#pragma unroll
                        for (int mt = 0; mt < 4; mt++)
#pragma unroll
                            for (int nt = 0; nt < 8; nt++) {
                                asm volatile(
                                    "mma.sync.aligned.m16n8k8.row.col.f32.tf32.tf32.f32 "
                                    "{%0,%1,%2,%3}, {%4,%5,%6,%7}, {%8,%9}, {%0,%1,%2,%3};"
                                    : "+f"(acc[mt][nt][0]), "+f"(acc[mt][nt][1]),
                                      "+f"(acc[mt][nt][2]), "+f"(acc[mt][nt][3])
                                    : "r"(a[mt][0]), "r"(a[mt][1]), "r"(a[mt][2]), "r"(a[mt][3]),
                                      "r"(b[nt][0]), "r"(b[nt][1]));
                            }
                    }
                }
            }
            __syncthreads();

            if (wid < 8) {
#pragma unroll
                for (int mt = 0; mt < 4; mt++) {
                    const int row0 = m0 + wm + mt * 16 + g;
#pragma unroll
                    for (int nt = 0; nt < 8; nt++) {
                        const int col0 = n0b + h * 256 + wn + nt * 8 + t4l * 2;
                        const float2 bv = *reinterpret_cast<const float2*>(bias + col0);
                        float2 v0, v1;
                        v0.x = acc[mt][nt][0] + bv.x;
                        v0.y = acc[mt][nt][1] + bv.y;
                        v1.x = acc[mt][nt][2] + bv.x;
                        v1.y = acc[mt][nt][3] + bv.y;
                        *reinterpret_cast<float2*>(out + (size_t)row0 * N + col0) = v0;
                        *reinterpret_cast<float2*>(out + (size_t)(row0 + 8) * N + col0) = v1;
                    }
                }
            }
            __syncthreads();
        }
    }
#endif
}

// ---------------------------------------------------------------------------
// host: tensor map encode (dlopen'd driver API) + launch
// ---------------------------------------------------------------------------
typedef CUresult (*PFN_tmEncode)(
    CUtensorMap*, CUtensorMapDataType, cuuint32_t, void*,
    const cuuint64_t*, const cuuint64_t*, const cuuint32_t*, const cuuint32_t*,
    CUtensorMapInterleave, CUtensorMapSwizzle, CUtensorMapL2promotion,
    CUtensorMapFloatOOBfill);

static PFN_tmEncode get_encoder() {
    static PFN_tmEncode fn = nullptr;
    if (!fn) {
        void* h = dlopen("libcuda.so.1", RTLD_NOW | RTLD_GLOBAL);
        if (!h) h = dlopen("libcuda.so", RTLD_NOW | RTLD_GLOBAL);
        if (h) fn = (PFN_tmEncode)dlsym(h, "cuTensorMapEncodeTiled");
    }
    return fn;
}

static void encode_map(PFN_tmEncode enc, CUtensorMap* tm, void* base,
                       uint64_t rows, uint64_t cols_elems) {
    cuuint64_t dims[3]    = {cols_elems, rows, 1};
    cuuint64_t strides[2] = {cols_elems * 4, rows * cols_elems * 4};
    cuuint32_t box[3]     = {32, 128, 1};     // 32 f32 = 128 B (SW128 limit)
    cuuint32_t estr[3]    = {1, 1, 1};
    enc(tm, CU_TENSOR_MAP_DATA_TYPE_FLOAT32, 3, base, dims, strides, box, estr,
        CU_TENSOR_MAP_INTERLEAVE_NONE, CU_TENSOR_MAP_SWIZZLE_128B,
        CU_TENSOR_MAP_L2_PROMOTION_L2_128B, CU_TENSOR_MAP_FLOAT_OOB_FILL_NONE);
}

extern "C" void kernel_launch(void* const* d_in, const int* in_sizes, int n_in,
                              void* d_out, int out_size) {
    const float* x    = (const float*)d_in[0];
    const float* w    = (const float*)d_in[1];
    const float* bias = (const float*)d_in[2];
    const float* mask = (const float*)d_in[3];
    float* out = (float*)d_out;

    const int N = in_sizes[2];                  // 4096
    const int K = in_sizes[1] / N;              // 4096
    const int M = in_sizes[0] / K;              // 8192

    static CUtensorMap tmx, tmw;
    PFN_tmEncode enc = get_encoder();
    void* wm_ptr = nullptr;
    cudaGetSymbolAddress(&wm_ptr, g_wm);
    if (enc) {
        encode_map(enc, &tmx, (void*)x, (uint64_t)M, (uint64_t)K);
        encode_map(enc, &tmw, wm_ptr,   (uint64_t)N, (uint64_t)K);
    }

    cudaFuncSetAttribute(masked_gemm_kernel,
                         cudaFuncAttributeMaxDynamicSharedMemorySize, SMEM_TOTAL);
    masked_gemm_kernel<<<NCTAS, THREADS, SMEM_TOTAL>>>(x, w, mask, bias, out,
                                                       M, N, K, tmx, tmw);

    {
        const int total4 = NSPLIT * 256 * 512 / 4;
        reduce_kernel<<<(total4 + 255) / 256, 256>>>(out, N);
    }
}

// round 12
// speedup vs baseline: 1.0424x; 1.0424x over previous
#include <cuda_runtime.h>
#include <cuda.h>
#include <dlfcn.h>
#include <cstdint>
#include <cstddef>

// ============================================================================
// MaskedLinear: y = x @ (W*mask)^T + b ; M=8192, K=4096, N=4096 fp32.
//
// prep_w : g_wm = cvt.rna.tf32(W*mask)
// gemm   : PERSISTENT cg2 tcgen05 kind::tf32 SS GEMM, pair tile 256x512,
//          BK=32, 4-stage ring fed by cta_group::2 TMA.
//          74 pairs x 3 full tiles (0..221); remainder tiles 222..255 SPLIT-K:
//          owner pair s (<34): K[0:2048) -> out (+bias);
//          helper pair 34+s   : K[2048:4096) -> g_part (raw).
//          NO cross-pair sync; reduce_kernel adds g_part into out afterwards.
//          Epilogue: single LDTM.x16 per wait, uniform body.
// reduce : out += g_part over the 34 split tiles (~8 us).
// Fallback (non-103a PTX pass; never selected on GB300): mma.sync tf32.
//
// This is the R8 configuration (measured 340.2 us) restored verbatim after
// R9/R10/R11 probes (2xLDTM, desc precompute, fused prep) all regressed.
// ============================================================================

#define SWZ(o) ((o) ^ (((o) >> 3) & 0x70))

static constexpr int BK = 32;                 // floats per K-chunk (128 B)
static constexpr int THREADS = 288;           // warps 0-7 epilogue, warp 8 ctrl
static constexpr int STAGES = 4;

static constexpr int A_BYTES  = 128 * 128;    // 16 KB
static constexpr int B0_BYTES = 128 * 128;
static constexpr int B1_BYTES = 128 * 128;
static constexpr int STAGE_BYTES = A_BYTES + B0_BYTES + B1_BYTES;     // 48 KB
static constexpr int SMEM_STAGE0 = 1024;
static constexpr int SMEM_TOTAL = SMEM_STAGE0 + STAGES * STAGE_BYTES; // 197632
static constexpr int TMEM_COLS = 512;
static constexpr uint32_t STAGE_TX = (uint32_t)STAGE_BYTES * 2;       // both CTAs

// idesc kind::tf32 cg2: dfmt=F32(1)<<4, atype=TF32(2)<<7, btype=TF32(2)<<10,
// N=256 -> 32<<17, M=256 -> 16<<24.
static constexpr uint32_t IDESC =
    (1u << 4) | (2u << 7) | (2u << 10) | (32u << 17) | (16u << 24);

// SW128 K-major smem descriptor: layout=SW128(2), version=1, SBO=64, LBO=1
static constexpr uint64_t DESC_BASE =
    (2ULL << 61) | (1ULL << 46) | (64ULL << 32) | (1ULL << 16);

// mbar offsets
#define FULL_OFF(s)  (16u + (uint32_t)(s) * 8u)    // leader, tx-based
#define DONE_OFF(s)  (48u + (uint32_t)(s) * 8u)    // both CTAs, count 1
#define MMAD_OFF(p)  (88u + (uint32_t)(p) * 8u)    // both CTAs, count 1
#define EPI_OFF(p)   (104u + (uint32_t)(p) * 8u)   // leader, count 16

// --- fallback layout (base sm_103 pass only; never runs on GB300) ---
static constexpr int FB_A_BYTES = 128 * 128;
static constexpr int FB_B_BYTES = 256 * 128;
static constexpr int FB_STAGE_BYTES = FB_A_BYTES + FB_B_BYTES;   // 49152
static constexpr int NLOAD = 256;

static constexpr int NSPLIT = 34;              // split tiles 222..255

__device__ float g_wm[4096ull * 4096ull];      // 64 MiB scratch
__device__ float g_part[(size_t)NSPLIT * 256 * 512];   // split-K partials

// ---------------------------------------------------------------------------
// portable helpers
// ---------------------------------------------------------------------------
__device__ __forceinline__ uint32_t smem_u32(const void* p) {
    uint32_t a;
    asm("{ .reg .u64 t; cvta.to.shared.u64 t, %1; cvt.u32.u64 %0, t; }"
        : "=r"(a) : "l"(p));
    return a;
}

__device__ __forceinline__ float to_tf32_rn(float x) {
    uint32_t u;
    asm("cvt.rna.tf32.f32 %0, %1;" : "=r"(u) : "f"(x));
    return __uint_as_float(u);
}

__device__ __forceinline__ void cp16(uint32_t s, const float* g) {
    asm volatile("cp.async.cg.shared.global [%0], [%1], 16;"
                 :: "r"(s), "l"(__cvta_generic_to_global((const void*)g)));
}

__device__ __forceinline__ uint32_t lds_u32(uint32_t addr) {
    uint32_t v;
    asm volatile("ld.shared.b32 %0, [%1];" : "=r"(v) : "r"(addr));
    return v;
}

#define CLUSTER_SYNC() do {                                          \
    asm volatile("barrier.cluster.arrive.aligned;" ::: "memory");    \
    asm volatile("barrier.cluster.wait.aligned;" ::: "memory");      \
} while (0)

// ---------------------------------------------------------------------------
// sm_103a-only pieces
// ---------------------------------------------------------------------------
#if defined(__CUDA_ARCH_FEAT_SM103_ALL) || defined(__CUDA_ARCH_FEAT_SM100_ALL) || !defined(__CUDA_ARCH__)

__device__ __forceinline__ uint32_t elect_one() {
    uint32_t p;
    asm volatile(
        "{\n\t.reg .pred p;\n\telect.sync _|p, 0xFFFFFFFF;\n\t"
        "selp.b32 %0, 1, 0, p;\n\t}" : "=r"(p));
    return p;
}

__device__ __forceinline__ void mma_tf32_cg2(uint32_t d_tmem, uint64_t a_desc,
                                             uint64_t b_desc, uint32_t en) {
#if defined(__CUDA_ARCH__)
    asm volatile(
        "{\n\t.reg .pred p;\n\tsetp.ne.u32 p, %6, 0;\n\t"
        "tcgen05.mma.cta_group::2.kind::tf32 [%0], %1, %2, %3, "
        "{%4, %4, %4, %4, %4, %4, %4, %4}, p;\n\t}"
        :: "r"(d_tmem), "l"(a_desc), "l"(b_desc), "r"(IDESC),
           "r"(0u), "r"(0u), "r"(en)
        : "memory");
#endif
}

__device__ __forceinline__ void tma_cg2(uint32_t dst, const void* map,
                                        int cx, int cy, uint32_t mbar) {
#if defined(__CUDA_ARCH__)
    asm volatile(
        "{\n\t.reg .b32 lb;\n\t.reg .b32 cz;\n\tmov.b32 cz, 0;\n\t"
        "and.b32 lb, %4, 0xFEFFFFFF;\n\t"
        "cp.async.bulk.tensor.3d.cta_group::2.shared::cluster.global"
        ".tile.mbarrier::complete_tx::bytes [%0], [%1, {%2, %3, cz}], [lb];\n\t}"
        :: "r"(dst), "l"(map), "r"(cx), "r"(cy), "r"(mbar)
        : "memory");
#endif
}

#define MBARRIER_INIT(addr, cnt) \
    asm volatile("mbarrier.init.shared.b64 [%0], %1;" :: "r"(addr), "r"(cnt) : "memory")

#define MBARRIER_EXPECT_TX(addr, bytes) \
    asm volatile("mbarrier.arrive.expect_tx.shared.b64 _, [%0], %1;" \
        :: "r"((uint32_t)(addr)), "r"((uint32_t)(bytes)) : "memory")

#define MBARRIER_WAIT_PARITY(addr, ph) do {                                   \
    uint32_t _m = (uint32_t)(addr); uint32_t _p = (uint32_t)(ph);             \
    uint32_t _d;                                                              \
    asm volatile("{\n\t.reg .pred p;\n\t"                                     \
        "mbarrier.try_wait.parity.acquire.cta.shared::cta.b64 p, [%1], %2;\n\t" \
        "selp.b32 %0, 1, 0, p;\n\t}" : "=r"(_d) : "r"(_m), "r"(_p) : "memory"); \
    if (!_d) {                                                                \
        asm volatile("{\n\t.reg .pred P1;\n\t"                                \
            "WL_%=:\n\t"                                                      \
            "mbarrier.try_wait.parity.acquire.cta.shared::cta.b64 P1, [%0], %1, 0x989680;\n\t" \
            "@P1 bra.uni WD_%=;\n\t"                                          \
            "bra.uni WL_%=;\n\t"                                              \
            "WD_%=:\n\t}" :: "r"(_m), "r"(_p) : "memory");                    \
    }                                                                         \
} while (0)

#define MBARRIER_ARRIVE_LOCAL(addr)                                           \
    asm volatile("mbarrier.arrive.shared.b64 _, [%0];"                        \
        :: "r"((uint32_t)(addr)) : "memory")

#define MBARRIER_ARRIVE_RANK0(addr)                                           \
    asm volatile("{\n\t.reg .b32 r;\n\t"                                      \
        "mapa.shared::cluster.u32 r, %0, 0;\n\t"                              \
        "mbarrier.arrive.shared::cluster.b64 _, [r];\n\t}"                    \
        :: "r"((uint32_t)(addr)) : "memory")

#define TCGEN05_COMMIT_MC_CG2(addr, mask)                                     \
    asm volatile("tcgen05.commit.cta_group::2.mbarrier::arrive::one.shared::cluster.multicast::cluster.b64 [%0], %1;" \
        :: "r"((uint32_t)(addr)), "h"((uint16_t)(mask)) : "memory")

#define LDTM_X16(r, addr)                                                     \
    asm volatile("tcgen05.ld.sync.aligned.32x32b.x16.b32 "                    \
        "{%0, %1, %2, %3, %4, %5, %6, %7, "                                   \
        " %8, %9, %10, %11, %12, %13, %14, %15}, [%16];"                      \
        : "=r"((r)[0]),  "=r"((r)[1]),  "=r"((r)[2]),  "=r"((r)[3]),          \
          "=r"((r)[4]),  "=r"((r)[5]),  "=r"((r)[6]),  "=r"((r)[7]),          \
          "=r"((r)[8]),  "=r"((r)[9]),  "=r"((r)[10]), "=r"((r)[11]),         \
          "=r"((r)[12]), "=r"((r)[13]), "=r"((r)[14]), "=r"((r)[15])          \
        : "r"(addr))

// chunk c -> tile/k mapping and TMA issue (3 loads into stage buffer sa)
__device__ __forceinline__ void issue_tma_chunk(
    int c, int n3c, int pair, int NPAIRS, int t4, int k4,
    uint32_t sa, const CUtensorMap* tmx, const CUtensorMap* tmw,
    uint32_t mbar, int rank)
{
#if defined(__CUDA_ARCH__)
    int t, k;
    if (c < n3c) { t = pair + (c >> 7) * NPAIRS; k = c & 127; }
    else         { t = t4; k = k4 + (c - n3c); }
    const int mi = t & 31, ni = t >> 5;            // NT_M = 32
    tma_cg2(sa,                      tmx, k * 32, mi * 256 + rank * 128, mbar);
    tma_cg2(sa + A_BYTES,            tmw, k * 32, ni * 512 + rank * 128, mbar);
    tma_cg2(sa + A_BYTES + B0_BYTES, tmw, k * 32, ni * 512 + 256 + rank * 128, mbar);
#endif
}

#endif // sm_103a-only pieces

// ---------------------------------------------------------------------------
// prep kernel
// ---------------------------------------------------------------------------
__global__ void prep_w_kernel(const float4* __restrict__ w,
                              const float4* __restrict__ m, int n4) {
    int i = blockIdx.x * blockDim.x + threadIdx.x;
    if (i >= n4) return;
    float4 a = w[i], b = m[i], r;
    r.x = to_tf32_rn(a.x * b.x);
    r.y = to_tf32_rn(a.y * b.y);
    r.z = to_tf32_rn(a.z * b.z);
    r.w = to_tf32_rn(a.w * b.w);
    reinterpret_cast<float4*>(g_wm)[i] = r;
}

// ---------------------------------------------------------------------------
// reduce kernel: out += g_part over the 34 split tiles
// ---------------------------------------------------------------------------
__global__ void reduce_kernel(float* __restrict__ out, int N) {
    const int total4 = NSPLIT * 256 * 512 / 4;        // 1,114,112
    int i = blockIdx.x * blockDim.x + threadIdx.x;
    if (i >= total4) return;
    const int e = i * 4;
    const int s = e / (256 * 512);
    const int rem = e % (256 * 512);
    const int row = rem >> 9, col = rem & 511;
    const int t = 222 + s;
    const int mi = t & 31, ni = t >> 5;
    float4 p = reinterpret_cast<const float4*>(g_part)[i];
    float4* op = reinterpret_cast<float4*>(
        out + (size_t)(mi * 256 + row) * N + ni * 512 + col);
    float4 v = *op;
    v.x += p.x; v.y += p.y; v.z += p.z; v.w += p.w;
    *op = v;
}

// ---------------------------------------------------------------------------
// fallback stage load (base pass only)
// ---------------------------------------------------------------------------
__device__ __forceinline__ void load_stage_fb(uint32_t sb, int buf,
                                              const float* gA, const float* gB,
                                              int K, int ltid) {
    const uint32_t sa  = sb + SMEM_STAGE0 + buf * FB_STAGE_BYTES;
    const uint32_t sbm = sa + FB_A_BYTES;
#pragma unroll
    for (int i = 0; i < 4; i++) {
        int u = ltid + i * NLOAD;
        int row = u >> 3, seg = u & 7;
        uint32_t off = (uint32_t)(row * 128 + seg * 16);
        cp16(sa + SWZ(off), gA + (size_t)row * K + seg * 4);
    }
#pragma unroll
    for (int i = 0; i < 8; i++) {
        int u = ltid + i * NLOAD;
        int row = u >> 3, seg = u & 7;
        uint32_t off = (uint32_t)(row * 128 + seg * 16);
        cp16(sbm + SWZ(off), gB + (size_t)row * K + seg * 4);
    }
    asm volatile("cp.async.commit_group;" ::: "memory");
}

// ---------------------------------------------------------------------------
// main GEMM kernel — persistent, TMA-fed cg2, split-K (no cross-pair sync)
// ---------------------------------------------------------------------------
__global__ void __launch_bounds__(THREADS, 1) __cluster_dims__(2, 1, 1)
masked_gemm_kernel(const float* __restrict__ x, const float* __restrict__ bias,
                   float* __restrict__ out, int M, int N, int K,
                   const __grid_constant__ CUtensorMap tmx,
                   const __grid_constant__ CUtensorMap tmw) {
    extern __shared__ char smem[];
    const uint32_t sb = smem_u32(smem);
    const int tid = threadIdx.x;
    const int wid = tid >> 5;
    const int lid = tid & 31;
    const int rank = blockIdx.x & 1;
    const int pair = blockIdx.x >> 1;
    const int NPAIRS = (int)(gridDim.x >> 1);          // 74

#if defined(__CUDA_ARCH_FEAT_SM103_ALL) || defined(__CUDA_ARCH_FEAT_SM100_ALL)
    // ======================== persistent TMA+cg2 path ======================
    const bool has4   = (pair < 2 * NSPLIT);           // pairs 0..67
    const int  s34    = (pair < NSPLIT) ? pair : pair - NSPLIT;
    const int  t4     = 222 + s34;
    const int  k4     = (pair < NSPLIT) ? 0 : 64;      // owner K-lo / helper K-hi
    const int  n3c    = 3 * 128;
    const int  tot    = n3c + (has4 ? 64 : 0);
    const int  n_items = has4 ? 4 : 3;

    if (wid == 8) {
        asm volatile("tcgen05.alloc.cta_group::2.sync.aligned.shared::cta.b32 [%0], %1;"
                     :: "r"(sb), "r"((uint32_t)TMEM_COLS) : "memory");
        asm volatile("tcgen05.relinquish_alloc_permit.cta_group::2.sync.aligned;");
    }
    if (tid == 0) {
#pragma unroll
        for (int s = 0; s < STAGES; s++) {
            MBARRIER_INIT(sb + FULL_OFF(s), 1);
            MBARRIER_INIT(sb + DONE_OFF(s), 1);
        }
        MBARRIER_INIT(sb + MMAD_OFF(0), 1);
        MBARRIER_INIT(sb + MMAD_OFF(1), 1);
        MBARRIER_INIT(sb + EPI_OFF(0), 16);
        MBARRIER_INIT(sb + EPI_OFF(1), 16);
    }
    __syncthreads();
    uint32_t tmem;
    asm volatile("ld.shared.b32 %0, [%1];" : "=r"(tmem) : "r"(sb));
    CLUSTER_SYNC();

    if (wid == 8) {
        if (elect_one()) {
            if (rank == 0) {
                for (int c = 0; c < 3; c++) {
                    const uint32_t sa = sb + SMEM_STAGE0 + (c & 3) * STAGE_BYTES;
                    MBARRIER_EXPECT_TX(sb + FULL_OFF(c & 3), STAGE_TX);
                    issue_tma_chunk(c, n3c, pair, NPAIRS, t4, k4, sa,
                                    &tmx, &tmw, sb + FULL_OFF(c & 3), rank);
                }
                for (int c = 0; c < tot; c++) {
                    const int s = c & 3;
                    const int it = c >> 7;
                    MBARRIER_WAIT_PARITY(sb + FULL_OFF(s), (c >> 2) & 1);
                    if ((c & 127) == 0 && it >= 1) {
                        const int pt = it - 1;
                        MBARRIER_WAIT_PARITY(sb + EPI_OFF(pt & 1), (pt >> 1) & 1);
                    }
                    const uint32_t sa = sb + SMEM_STAGE0 + s * STAGE_BYTES;
                    const uint64_t ad  = DESC_BASE | ((sa >> 4) & 0x3FFF);
                    const uint64_t b0d = DESC_BASE | (((sa + A_BYTES) >> 4) & 0x3FFF);
                    const uint64_t b1d = DESC_BASE | (((sa + A_BYTES + B0_BYTES) >> 4) & 0x3FFF);
                    const uint32_t nf = (uint32_t)((c & 127) != 0);
#pragma unroll
                    for (int ks = 0; ks < 4; ks++) {
                        uint32_t e = nf | (uint32_t)(ks > 0);
                        mma_tf32_cg2(tmem,        ad + ks * 2, b0d + ks * 2, e);
                        mma_tf32_cg2(tmem + 256u, ad + ks * 2, b1d + ks * 2, e);
                    }
                    TCGEN05_COMMIT_MC_CG2(sb + DONE_OFF(s), 0x3);
                    if (((c & 127) == 127) || (c == tot - 1)) {
                        TCGEN05_COMMIT_MC_CG2(sb + MMAD_OFF(it & 1), 0x3);
                    }
                    if (c >= 1) {
                        MBARRIER_WAIT_PARITY(sb + DONE_OFF((c - 1) & 3),
                                             ((c - 1) >> 2) & 1);
                    }
                    const int cn = c + 3;
                    if (cn < tot) {
                        const uint32_t sn = sb + SMEM_STAGE0 + (cn & 3) * STAGE_BYTES;
                        MBARRIER_EXPECT_TX(sb + FULL_OFF(cn & 3), STAGE_TX);
                        issue_tma_chunk(cn, n3c, pair, NPAIRS, t4, k4, sn,
                                        &tmx, &tmw, sb + FULL_OFF(cn & 3), rank);
                    }
                }
            } else {
                // follower: pure TMA issue, gated on local done ring
                for (int c = 0; c < tot; c++) {
                    if (c >= STAGES) {
                        MBARRIER_WAIT_PARITY(sb + DONE_OFF((c - 4) & 3),
                                             ((c - 4) >> 2) & 1);
                    }
                    const uint32_t sa = sb + SMEM_STAGE0 + (c & 3) * STAGE_BYTES;
                    issue_tma_chunk(c, n3c, pair, NPAIRS, t4, k4, sa,
                                    &tmx, &tmw, sb + FULL_OFF(c & 3), rank);
                }
            }
        }
    } else {
        // ------ epilogue warps: UNIFORM body, single LDTM.x16 per wait -----
        const int sub = wid & 3;
        const int half = wid >> 2;
        const int prow = rank * 128 + sub * 32 + lid;
        for (int it = 0; it < n_items; it++) {
            MBARRIER_WAIT_PARITY(sb + MMAD_OFF(it & 1), (it >> 1) & 1);
            asm volatile("tcgen05.fence::after_thread_sync;" ::: "memory");
            const int t = (it < 3) ? (pair + it * NPAIRS) : t4;
            const int mi = t & 31, ni = t >> 5;
            const bool is_helper = (it == 3) && (pair >= NSPLIT);

            float* orow;
            float bw;
            if (is_helper) {
                orow = g_part + ((size_t)s34 * 256 + prow) * 512;
                bw = 0.0f;
            } else {
                orow = out + (size_t)(mi * 256 + prow) * N + ni * 512;
                bw = 1.0f;
            }
            const float* brow = bias + ni * 512;

#pragma unroll
            for (int cc = 0; cc < 256; cc += 16) {
                const int col = half * 256 + cc;
                uint32_t r[16];
                LDTM_X16(r, tmem + (uint32_t)col);
                asm volatile("tcgen05.wait::ld.sync.aligned;" ::: "memory");
                const float4* bp = reinterpret_cast<const float4*>(brow + col);
                float4* op = reinterpret_cast<float4*>(orow + col);
#pragma unroll
                for (int j = 0; j < 4; j++) {
                    float4 bv = bp[j];
                    float4 v;
                    v.x = __uint_as_float(r[4 * j + 0]) + bw * bv.x;
                    v.y = __uint_as_float(r[4 * j + 1]) + bw * bv.y;
                    v.z = __uint_as_float(r[4 * j + 2]) + bw * bv.z;
                    v.w = __uint_as_float(r[4 * j + 3]) + bw * bv.w;
                    op[j] = v;
                }
            }
            asm volatile("tcgen05.fence::before_thread_sync;" ::: "memory");
            if (elect_one()) {
                if (rank == 0) MBARRIER_ARRIVE_LOCAL(sb + EPI_OFF(it & 1));
                else           MBARRIER_ARRIVE_RANK0(sb + EPI_OFF(it & 1));
            }
        }
    }

    __syncthreads();
    CLUSTER_SYNC();
    if (wid == 8) {
        asm volatile("tcgen05.dealloc.cta_group::2.sync.aligned.b32 %0, %1;"
                     :: "r"(tmem), "r"((uint32_t)TMEM_COLS));
    }
    CLUSTER_SYNC();

#else
    // ======================= mma.sync tf32 fallback ========================
    // Full-K over all 256 tiles; also zero g_part so reduce_kernel is a no-op.
    for (int i = blockIdx.x * blockDim.x + threadIdx.x;
         i < NSPLIT * 256 * 512 / 4; i += gridDim.x * blockDim.x) {
        reinterpret_cast<float4*>(g_part)[i] = make_float4(0.f, 0.f, 0.f, 0.f);
    }
    const int wm = (wid & 1) * 64;
    const int wn = ((wid >> 1) & 3) * 64;
    const int g  = lid >> 2;
    const int t4l = lid & 3;
    const int KCH = K / BK;

    for (int t = pair; t < 256; t += NPAIRS) {
        const int mi = t & 31, ni = t >> 5;
        const int m0 = mi * 256 + rank * 128;
        const int n0b = ni * 512;
        const float* gA0 = x + (size_t)m0 * K;

        for (int h = 0; h < 2; h++) {
            const float* gB0 = g_wm + (size_t)(n0b + h * 256) * K;

            float acc[4][8][4];
#pragma unroll
            for (int i = 0; i < 4; i++)
#pragma unroll
                for (int j = 0; j < 8; j++)
#pragma unroll
                    for (int c = 0; c < 4; c++) acc[i][j][c] = 0.0f;

            if (tid < NLOAD) {
#pragma unroll
                for (int s = 0; s < 3; s++)
                    load_stage_fb(sb, s, gA0 + s * BK, gB0 + s * BK, K, tid);
            }

            for (int k = 0; k < KCH; k++) {
                if (tid < NLOAD) {
                    int pend = KCH - 1 - k; if (pend > 2) pend = 2;
                    if (pend <= 0)      asm volatile("cp.async.wait_group 0;" ::: "memory");
                    else if (pend == 1) asm volatile("cp.async.wait_group 1;" ::: "memory");
                    else                asm volatile("cp.async.wait_group 2;" ::: "memory");
                }
                __syncthreads();

                if (tid < NLOAD && k + 3 < KCH) {
                    const int c = k + 3;
                    load_stage_fb(sb, (k + 3) & 3, gA0 + (size_t)c * BK,
                                  gB0 + (size_t)c * BK, K, tid);
                }

                if (wid < 8) {
                    const uint32_t sa = sb + SMEM_STAGE0 + (k & 3) * FB_STAGE_BYTES;
                    const uint32_t sB = sa + FB_A_BYTES;
#pragma unroll
                    for (int k8 = 0; k8 < 4; k8++) {
                        const int kc = k8 * 8;
                        uint32_t a[4][4];
#pragma unroll
                        for (int mt = 0; mt < 4; mt++) {
                            const int r0 = wm + mt * 16 + g;
                            const int c0 = kc + t4l;
                            a[mt][0] = lds_u32(sa + SWZ((uint32_t)(r0 * 128 + c0 * 4)));
                            a[mt][1] = lds_u32(sa + SWZ((uint32_t)((r0 + 8) * 128 + c0 * 4)));
                            a[mt][2] = lds_u32(sa + SWZ((uint32_t)(r0 * 128 + (c0 + 4) * 4)));
                            a[mt][3] = lds_u32(sa + SWZ((uint32_t)((r0 + 8) * 128 + (c0 + 4) * 4)));
                        }
                        uint32_t b[8][2];
#pragma unroll
                        for (int nt = 0; nt < 8; nt++) {
                            const int n = wn + nt * 8 + g;
                            const int ck = kc + t4l;
                            b[nt][0] = lds_u32(sB + SWZ((uint32_t)(n * 128 + ck * 4)));
                            b[nt][1] = lds_u32(sB + SWZ((uint32_t)(n * 128 + (ck + 4) * 4)));
                        }
#pragma unroll
                        for (int mt = 0; mt < 4; mt++)
#pragma unroll
                            for (int nt = 0; nt < 8; nt++) {
                                asm volatile(
                                    "mma.sync.aligned.m16n8k8.row.col.f32.tf32.tf32.f32 "
                                    "{%0,%1,%2,%3}, {%4,%5,%6,%7}, {%8,%9}, {%0,%1,%2,%3};"
                                    : "+f"(acc[mt][nt][0]), "+f"(acc[mt][nt][1]),
                                      "+f"(acc[mt][nt][2]), "+f"(acc[mt][nt][3])
                                    : "r"(a[mt][0]), "r"(a[mt][1]), "r"(a[mt][2]), "r"(a[mt][3]),
                                      "r"(b[nt][0]), "r"(b[nt][1]));
                            }
                    }
                }
            }
            __syncthreads();

            if (wid < 8) {
#pragma unroll
                for (int mt = 0; mt < 4; mt++) {
                    const int row0 = m0 + wm + mt * 16 + g;
#pragma unroll
                    for (int nt = 0; nt < 8; nt++) {
                        const int col0 = n0b + h * 256 + wn + nt * 8 + t4l * 2;
                        const float2 bv = *reinterpret_cast<const float2*>(bias + col0);
                        float2 v0, v1;
                        v0.x = acc[mt][nt][0] + bv.x;
                        v0.y = acc[mt][nt][1] + bv.y;
                        v1.x = acc[mt][nt][2] + bv.x;
                        v1.y = acc[mt][nt][3] + bv.y;
                        *reinterpret_cast<float2*>(out + (size_t)row0 * N + col0) = v0;
                        *reinterpret_cast<float2*>(out + (size_t)(row0 + 8) * N + col0) = v1;
                    }
                }
            }
            __syncthreads();
        }
    }
#endif
}

// ---------------------------------------------------------------------------
// host: tensor map encode (dlopen'd driver API) + launch
// ---------------------------------------------------------------------------
typedef CUresult (*PFN_tmEncode)(
    CUtensorMap*, CUtensorMapDataType, cuuint32_t, void*,
    const cuuint64_t*, const cuuint64_t*, const cuuint32_t*, const cuuint32_t*,
    CUtensorMapInterleave, CUtensorMapSwizzle, CUtensorMapL2promotion,
    CUtensorMapFloatOOBfill);

static PFN_tmEncode get_encoder() {
    static PFN_tmEncode fn = nullptr;
    if (!fn) {
        void* h = dlopen("libcuda.so.1", RTLD_NOW | RTLD_GLOBAL);
        if (!h) h = dlopen("libcuda.so", RTLD_NOW | RTLD_GLOBAL);
        if (h) fn = (PFN_tmEncode)dlsym(h, "cuTensorMapEncodeTiled");
    }
    return fn;
}

static void encode_map(PFN_tmEncode enc, CUtensorMap* tm, void* base,
                       uint64_t rows, uint64_t cols_elems) {
    cuuint64_t dims[3]    = {cols_elems, rows, 1};
    cuuint64_t strides[2] = {cols_elems * 4, rows * cols_elems * 4};
    cuuint32_t box[3]     = {32, 128, 1};     // 32 f32 = 128 B (SW128 limit)
    cuuint32_t estr[3]    = {1, 1, 1};
    enc(tm, CU_TENSOR_MAP_DATA_TYPE_FLOAT32, 3, base, dims, strides, box, estr,
        CU_TENSOR_MAP_INTERLEAVE_NONE, CU_TENSOR_MAP_SWIZZLE_128B,
        CU_TENSOR_MAP_L2_PROMOTION_L2_128B, CU_TENSOR_MAP_FLOAT_OOB_FILL_NONE);
}

extern "C" void kernel_launch(void* const* d_in, const int* in_sizes, int n_in,
                              void* d_out, int out_size) {
    const float* x    = (const float*)d_in[0];
    const float* w    = (const float*)d_in[1];
    const float* bias = (const float*)d_in[2];
    const float* mask = (const float*)d_in[3];
    float* out = (float*)d_out;

    const int N = in_sizes[2];                  // 4096
    const int K = in_sizes[1] / N;              // 4096
    const int M = in_sizes[0] / K;              // 8192

    {
        int n4 = (N * K) / 4;
        prep_w_kernel<<<(n4 + 255) / 256, 256>>>((const float4*)w,
                                                 (const float4*)mask, n4);
    }

    static CUtensorMap tmx, tmw;
    PFN_tmEncode enc = get_encoder();
    void* wm_ptr = nullptr;
    cudaGetSymbolAddress(&wm_ptr, g_wm);
    if (enc) {
        encode_map(enc, &tmx, (void*)x, (uint64_t)M, (uint64_t)K);
        encode_map(enc, &tmw, wm_ptr,   (uint64_t)N, (uint64_t)K);
    }

    cudaFuncSetAttribute(masked_gemm_kernel,
                         cudaFuncAttributeMaxDynamicSharedMemorySize, SMEM_TOTAL);
    masked_gemm_kernel<<<148, THREADS, SMEM_TOTAL>>>(x, bias, out, M, N, K,
                                                     tmx, tmw);

    {
        const int total4 = NSPLIT * 256 * 512 / 4;
        reduce_kernel<<<(total4 + 255) / 256, 256>>>(out, N);
    }
}

// round 13
// speedup vs baseline: 1.0477x; 1.0051x over previous
#include <cuda_runtime.h>
#include <cuda.h>
#include <dlfcn.h>
#include <cstdint>
#include <cstddef>

// ============================================================================
// MaskedLinear: y = x @ (W*mask)^T + b ; M=8192, K=4096, N=4096 fp32.
//
// prep_w : g_wm = cvt.rna.tf32(W*mask)
// gemm   : PERSISTENT cg2 tcgen05 kind::tf32 SS GEMM, pair tile 256x512,
//          BK=32, 4-stage ring fed by cta_group::2 TMA.
//          74 pairs x 3 full tiles (0..221); remainder tiles 222..255 SPLIT-K:
//          owner pair s (<34): K[0:2048) -> out (+bias);
//          helper pair 34+s   : K[2048:4096) -> g_part (raw).
//          NO cross-pair sync; reduce_kernel adds g_part into out afterwards.
//          Epilogue: single LDTM.x16 per wait, uniform body.
// reduce : out += g_part over the 34 split tiles (shift/mask indexing).
// Fallback (non-103a PTX pass; never selected on GB300): mma.sync tf32.
//
// R8 configuration (measured 340.2 / 341.8 us) — the session optimum after
// R9/R10/R11 probes (2xLDTM, desc precompute, fused prep) all regressed.
// ============================================================================

#define SWZ(o) ((o) ^ (((o) >> 3) & 0x70))

static constexpr int BK = 32;                 // floats per K-chunk (128 B)
static constexpr int THREADS = 288;           // warps 0-7 epilogue, warp 8 ctrl
static constexpr int STAGES = 4;

static constexpr int A_BYTES  = 128 * 128;    // 16 KB
static constexpr int B0_BYTES = 128 * 128;
static constexpr int B1_BYTES = 128 * 128;
static constexpr int STAGE_BYTES = A_BYTES + B0_BYTES + B1_BYTES;     // 48 KB
static constexpr int SMEM_STAGE0 = 1024;
static constexpr int SMEM_TOTAL = SMEM_STAGE0 + STAGES * STAGE_BYTES; // 197632
static constexpr int TMEM_COLS = 512;
static constexpr uint32_t STAGE_TX = (uint32_t)STAGE_BYTES * 2;       // both CTAs

// idesc kind::tf32 cg2: dfmt=F32(1)<<4, atype=TF32(2)<<7, btype=TF32(2)<<10,
// N=256 -> 32<<17, M=256 -> 16<<24.
static constexpr uint32_t IDESC =
    (1u << 4) | (2u << 7) | (2u << 10) | (32u << 17) | (16u << 24);

// SW128 K-major smem descriptor: layout=SW128(2), version=1, SBO=64, LBO=1
static constexpr uint64_t DESC_BASE =
    (2ULL << 61) | (1ULL << 46) | (64ULL << 32) | (1ULL << 16);

// mbar offsets
#define FULL_OFF(s)  (16u + (uint32_t)(s) * 8u)    // leader, tx-based
#define DONE_OFF(s)  (48u + (uint32_t)(s) * 8u)    // both CTAs, count 1
#define MMAD_OFF(p)  (88u + (uint32_t)(p) * 8u)    // both CTAs, count 1
#define EPI_OFF(p)   (104u + (uint32_t)(p) * 8u)   // leader, count 16

// --- fallback layout (base sm_103 pass only; never runs on GB300) ---
static constexpr int FB_A_BYTES = 128 * 128;
static constexpr int FB_B_BYTES = 256 * 128;
static constexpr int FB_STAGE_BYTES = FB_A_BYTES + FB_B_BYTES;   // 49152
static constexpr int NLOAD = 256;

static constexpr int NSPLIT = 34;              // split tiles 222..255

__device__ float g_wm[4096ull * 4096ull];      // 64 MiB scratch
__device__ float g_part[(size_t)NSPLIT * 256 * 512];   // split-K partials

// ---------------------------------------------------------------------------
// portable helpers
// ---------------------------------------------------------------------------
__device__ __forceinline__ uint32_t smem_u32(const void* p) {
    uint32_t a;
    asm("{ .reg .u64 t; cvta.to.shared.u64 t, %1; cvt.u32.u64 %0, t; }"
        : "=r"(a) : "l"(p));
    return a;
}

__device__ __forceinline__ float to_tf32_rn(float x) {
    uint32_t u;
    asm("cvt.rna.tf32.f32 %0, %1;" : "=r"(u) : "f"(x));
    return __uint_as_float(u);
}

__device__ __forceinline__ void cp16(uint32_t s, const float* g) {
    asm volatile("cp.async.cg.shared.global [%0], [%1], 16;"
                 :: "r"(s), "l"(__cvta_generic_to_global((const void*)g)));
}

__device__ __forceinline__ uint32_t lds_u32(uint32_t addr) {
    uint32_t v;
    asm volatile("ld.shared.b32 %0, [%1];" : "=r"(v) : "r"(addr));
    return v;
}

#define CLUSTER_SYNC() do {                                          \
    asm volatile("barrier.cluster.arrive.aligned;" ::: "memory");    \
    asm volatile("barrier.cluster.wait.aligned;" ::: "memory");      \
} while (0)

// ---------------------------------------------------------------------------
// sm_103a-only pieces
// ---------------------------------------------------------------------------
#if defined(__CUDA_ARCH_FEAT_SM103_ALL) || defined(__CUDA_ARCH_FEAT_SM100_ALL) || !defined(__CUDA_ARCH__)

__device__ __forceinline__ uint32_t elect_one() {
    uint32_t p;
    asm volatile(
        "{\n\t.reg .pred p;\n\telect.sync _|p, 0xFFFFFFFF;\n\t"
        "selp.b32 %0, 1, 0, p;\n\t}" : "=r"(p));
    return p;
}

__device__ __forceinline__ void mma_tf32_cg2(uint32_t d_tmem, uint64_t a_desc,
                                             uint64_t b_desc, uint32_t en) {
#if defined(__CUDA_ARCH__)
    asm volatile(
        "{\n\t.reg .pred p;\n\tsetp.ne.u32 p, %6, 0;\n\t"
        "tcgen05.mma.cta_group::2.kind::tf32 [%0], %1, %2, %3, "
        "{%4, %4, %4, %4, %4, %4, %4, %4}, p;\n\t}"
        :: "r"(d_tmem), "l"(a_desc), "l"(b_desc), "r"(IDESC),
           "r"(0u), "r"(0u), "r"(en)
        : "memory");
#endif
}

__device__ __forceinline__ void tma_cg2(uint32_t dst, const void* map,
                                        int cx, int cy, uint32_t mbar) {
#if defined(__CUDA_ARCH__)
    asm volatile(
        "{\n\t.reg .b32 lb;\n\t.reg .b32 cz;\n\tmov.b32 cz, 0;\n\t"
        "and.b32 lb, %4, 0xFEFFFFFF;\n\t"
        "cp.async.bulk.tensor.3d.cta_group::2.shared::cluster.global"
        ".tile.mbarrier::complete_tx::bytes [%0], [%1, {%2, %3, cz}], [lb];\n\t}"
        :: "r"(dst), "l"(map), "r"(cx), "r"(cy), "r"(mbar)
        : "memory");
#endif
}

#define MBARRIER_INIT(addr, cnt) \
    asm volatile("mbarrier.init.shared.b64 [%0], %1;" :: "r"(addr), "r"(cnt) : "memory")

#define MBARRIER_EXPECT_TX(addr, bytes) \
    asm volatile("mbarrier.arrive.expect_tx.shared.b64 _, [%0], %1;" \
        :: "r"((uint32_t)(addr)), "r"((uint32_t)(bytes)) : "memory")

#define MBARRIER_WAIT_PARITY(addr, ph) do {                                   \
    uint32_t _m = (uint32_t)(addr); uint32_t _p = (uint32_t)(ph);             \
    uint32_t _d;                                                              \
    asm volatile("{\n\t.reg .pred p;\n\t"                                     \
        "mbarrier.try_wait.parity.acquire.cta.shared::cta.b64 p, [%1], %2;\n\t" \
        "selp.b32 %0, 1, 0, p;\n\t}" : "=r"(_d) : "r"(_m), "r"(_p) : "memory"); \
    if (!_d) {                                                                \
        asm volatile("{\n\t.reg .pred P1;\n\t"                                \
            "WL_%=:\n\t"                                                      \
            "mbarrier.try_wait.parity.acquire.cta.shared::cta.b64 P1, [%0], %1, 0x989680;\n\t" \
            "@P1 bra.uni WD_%=;\n\t"                                          \
            "bra.uni WL_%=;\n\t"                                              \
            "WD_%=:\n\t}" :: "r"(_m), "r"(_p) : "memory");                    \
    }                                                                         \
} while (0)

#define MBARRIER_ARRIVE_LOCAL(addr)                                           \
    asm volatile("mbarrier.arrive.shared.b64 _, [%0];"                        \
        :: "r"((uint32_t)(addr)) : "memory")

#define MBARRIER_ARRIVE_RANK0(addr)                                           \
    asm volatile("{\n\t.reg .b32 r;\n\t"                                      \
        "mapa.shared::cluster.u32 r, %0, 0;\n\t"                              \
        "mbarrier.arrive.shared::cluster.b64 _, [r];\n\t}"                    \
        :: "r"((uint32_t)(addr)) : "memory")

#define TCGEN05_COMMIT_MC_CG2(addr, mask)                                     \
    asm volatile("tcgen05.commit.cta_group::2.mbarrier::arrive::one.shared::cluster.multicast::cluster.b64 [%0], %1;" \
        :: "r"((uint32_t)(addr)), "h"((uint16_t)(mask)) : "memory")

#define LDTM_X16(r, addr)                                                     \
    asm volatile("tcgen05.ld.sync.aligned.32x32b.x16.b32 "                    \
        "{%0, %1, %2, %3, %4, %5, %6, %7, "                                   \
        " %8, %9, %10, %11, %12, %13, %14, %15}, [%16];"                      \
        : "=r"((r)[0]),  "=r"((r)[1]),  "=r"((r)[2]),  "=r"((r)[3]),          \
          "=r"((r)[4]),  "=r"((r)[5]),  "=r"((r)[6]),  "=r"((r)[7]),          \
          "=r"((r)[8]),  "=r"((r)[9]),  "=r"((r)[10]), "=r"((r)[11]),         \
          "=r"((r)[12]), "=r"((r)[13]), "=r"((r)[14]), "=r"((r)[15])          \
        : "r"(addr))

// chunk c -> tile/k mapping and TMA issue (3 loads into stage buffer sa)
__device__ __forceinline__ void issue_tma_chunk(
    int c, int n3c, int pair, int NPAIRS, int t4, int k4,
    uint32_t sa, const CUtensorMap* tmx, const CUtensorMap* tmw,
    uint32_t mbar, int rank)
{
#if defined(__CUDA_ARCH__)
    int t, k;
    if (c < n3c) { t = pair + (c >> 7) * NPAIRS; k = c & 127; }
    else         { t = t4; k = k4 + (c - n3c); }
    const int mi = t & 31, ni = t >> 5;            // NT_M = 32
    tma_cg2(sa,                      tmx, k * 32, mi * 256 + rank * 128, mbar);
    tma_cg2(sa + A_BYTES,            tmw, k * 32, ni * 512 + rank * 128, mbar);
    tma_cg2(sa + A_BYTES + B0_BYTES, tmw, k * 32, ni * 512 + 256 + rank * 128, mbar);
#endif
}

#endif // sm_103a-only pieces

// ---------------------------------------------------------------------------
// prep kernel
// ---------------------------------------------------------------------------
__global__ void prep_w_kernel(const float4* __restrict__ w,
                              const float4* __restrict__ m, int n4) {
    int i = blockIdx.x * blockDim.x + threadIdx.x;
    if (i >= n4) return;
    float4 a = w[i], b = m[i], r;
    r.x = to_tf32_rn(a.x * b.x);
    r.y = to_tf32_rn(a.y * b.y);
    r.z = to_tf32_rn(a.z * b.z);
    r.w = to_tf32_rn(a.w * b.w);
    reinterpret_cast<float4*>(g_wm)[i] = r;
}

// ---------------------------------------------------------------------------
// reduce kernel: out += g_part over the 34 split tiles (shift/mask indexing)
// ---------------------------------------------------------------------------
__global__ void reduce_kernel(float* __restrict__ out, int N) {
    const int total4 = NSPLIT * 256 * 512 / 4;        // 1,114,112
    int i = blockIdx.x * blockDim.x + threadIdx.x;
    if (i >= total4) return;
    const int e = i << 2;
    const int s = e >> 17;                            // / (256*512)
    const int rem = e & 0x1FFFF;                      // % (256*512)
    const int row = rem >> 9, col = rem & 511;
    const int t = 222 + s;
    const int mi = t & 31, ni = t >> 5;
    float4 p = __ldg(reinterpret_cast<const float4*>(g_part) + i);
    float4* op = reinterpret_cast<float4*>(
        out + (size_t)(mi * 256 + row) * N + ni * 512 + col);
    float4 v = *op;
    v.x += p.x; v.y += p.y; v.z += p.z; v.w += p.w;
    *op = v;
}

// ---------------------------------------------------------------------------
// fallback stage load (base pass only)
// ---------------------------------------------------------------------------
__device__ __forceinline__ void load_stage_fb(uint32_t sb, int buf,
                                              const float* gA, const float* gB,
                                              int K, int ltid) {
    const uint32_t sa  = sb + SMEM_STAGE0 + buf * FB_STAGE_BYTES;
    const uint32_t sbm = sa + FB_A_BYTES;
#pragma unroll
    for (int i = 0; i < 4; i++) {
        int u = ltid + i * NLOAD;
        int row = u >> 3, seg = u & 7;
        uint32_t off = (uint32_t)(row * 128 + seg * 16);
        cp16(sa + SWZ(off), gA + (size_t)row * K + seg * 4);
    }
#pragma unroll
    for (int i = 0; i < 8; i++) {
        int u = ltid + i * NLOAD;
        int row = u >> 3, seg = u & 7;
        uint32_t off = (uint32_t)(row * 128 + seg * 16);
        cp16(sbm + SWZ(off), gB + (size_t)row * K + seg * 4);
    }
    asm volatile("cp.async.commit_group;" ::: "memory");
}

// ---------------------------------------------------------------------------
// main GEMM kernel — persistent, TMA-fed cg2, split-K (no cross-pair sync)
// ---------------------------------------------------------------------------
__global__ void __launch_bounds__(THREADS, 1) __cluster_dims__(2, 1, 1)
masked_gemm_kernel(const float* __restrict__ x, const float* __restrict__ bias,
                   float* __restrict__ out, int M, int N, int K,
                   const __grid_constant__ CUtensorMap tmx,
                   const __grid_constant__ CUtensorMap tmw) {
    extern __shared__ char smem[];
    const uint32_t sb = smem_u32(smem);
    const int tid = threadIdx.x;
    const int wid = tid >> 5;
    const int lid = tid & 31;
    const int rank = blockIdx.x & 1;
    const int pair = blockIdx.x >> 1;
    const int NPAIRS = (int)(gridDim.x >> 1);          // 74

#if defined(__CUDA_ARCH_FEAT_SM103_ALL) || defined(__CUDA_ARCH_FEAT_SM100_ALL)
    // ======================== persistent TMA+cg2 path ======================
    const bool has4   = (pair < 2 * NSPLIT);           // pairs 0..67
    const int  s34    = (pair < NSPLIT) ? pair : pair - NSPLIT;
    const int  t4     = 222 + s34;
    const int  k4     = (pair < NSPLIT) ? 0 : 64;      // owner K-lo / helper K-hi
    const int  n3c    = 3 * 128;
    const int  tot    = n3c + (has4 ? 64 : 0);
    const int  n_items = has4 ? 4 : 3;

    if (wid == 8) {
        asm volatile("tcgen05.alloc.cta_group::2.sync.aligned.shared::cta.b32 [%0], %1;"
                     :: "r"(sb), "r"((uint32_t)TMEM_COLS) : "memory");
        asm volatile("tcgen05.relinquish_alloc_permit.cta_group::2.sync.aligned;");
    }
    if (tid == 0) {
#pragma unroll
        for (int s = 0; s < STAGES; s++) {
            MBARRIER_INIT(sb + FULL_OFF(s), 1);
            MBARRIER_INIT(sb + DONE_OFF(s), 1);
        }
        MBARRIER_INIT(sb + MMAD_OFF(0), 1);
        MBARRIER_INIT(sb + MMAD_OFF(1), 1);
        MBARRIER_INIT(sb + EPI_OFF(0), 16);
        MBARRIER_INIT(sb + EPI_OFF(1), 16);
    }
    __syncthreads();
    uint32_t tmem;
    asm volatile("ld.shared.b32 %0, [%1];" : "=r"(tmem) : "r"(sb));
    CLUSTER_SYNC();

    if (wid == 8) {
        if (elect_one()) {
            if (rank == 0) {
                for (int c = 0; c < 3; c++) {
                    const uint32_t sa = sb + SMEM_STAGE0 + (c & 3) * STAGE_BYTES;
                    MBARRIER_EXPECT_TX(sb + FULL_OFF(c & 3), STAGE_TX);
                    issue_tma_chunk(c, n3c, pair, NPAIRS, t4, k4, sa,
                                    &tmx, &tmw, sb + FULL_OFF(c & 3), rank);
                }
                for (int c = 0; c < tot; c++) {
                    const int s = c & 3;
                    const int it = c >> 7;
                    MBARRIER_WAIT_PARITY(sb + FULL_OFF(s), (c >> 2) & 1);
                    if ((c & 127) == 0 && it >= 1) {
                        const int pt = it - 1;
                        MBARRIER_WAIT_PARITY(sb + EPI_OFF(pt & 1), (pt >> 1) & 1);
                    }
                    const uint32_t sa = sb + SMEM_STAGE0 + s * STAGE_BYTES;
                    const uint64_t ad  = DESC_BASE | ((sa >> 4) & 0x3FFF);
                    const uint64_t b0d = DESC_BASE | (((sa + A_BYTES) >> 4) & 0x3FFF);
                    const uint64_t b1d = DESC_BASE | (((sa + A_BYTES + B0_BYTES) >> 4) & 0x3FFF);
                    const uint32_t nf = (uint32_t)((c & 127) != 0);
#pragma unroll
                    for (int ks = 0; ks < 4; ks++) {
                        uint32_t e = nf | (uint32_t)(ks > 0);
                        mma_tf32_cg2(tmem,        ad + ks * 2, b0d + ks * 2, e);
                        mma_tf32_cg2(tmem + 256u, ad + ks * 2, b1d + ks * 2, e);
                    }
                    TCGEN05_COMMIT_MC_CG2(sb + DONE_OFF(s), 0x3);
                    if (((c & 127) == 127) || (c == tot - 1)) {
                        TCGEN05_COMMIT_MC_CG2(sb + MMAD_OFF(it & 1), 0x3);
                    }
                    if (c >= 1) {
                        MBARRIER_WAIT_PARITY(sb + DONE_OFF((c - 1) & 3),
                                             ((c - 1) >> 2) & 1);
                    }
                    const int cn = c + 3;
                    if (cn < tot) {
                        const uint32_t sn = sb + SMEM_STAGE0 + (cn & 3) * STAGE_BYTES;
                        MBARRIER_EXPECT_TX(sb + FULL_OFF(cn & 3), STAGE_TX);
                        issue_tma_chunk(cn, n3c, pair, NPAIRS, t4, k4, sn,
                                        &tmx, &tmw, sb + FULL_OFF(cn & 3), rank);
                    }
                }
            } else {
                // follower: pure TMA issue, gated on local done ring
                for (int c = 0; c < tot; c++) {
                    if (c >= STAGES) {
                        MBARRIER_WAIT_PARITY(sb + DONE_OFF((c - 4) & 3),
                                             ((c - 4) >> 2) & 1);
                    }
                    const uint32_t sa = sb + SMEM_STAGE0 + (c & 3) * STAGE_BYTES;
                    issue_tma_chunk(c, n3c, pair, NPAIRS, t4, k4, sa,
                                    &tmx, &tmw, sb + FULL_OFF(c & 3), rank);
                }
            }
        }
    } else {
        // ------ epilogue warps: UNIFORM body, single LDTM.x16 per wait -----
        const int sub = wid & 3;
        const int half = wid >> 2;
        const int prow = rank * 128 + sub * 32 + lid;
        for (int it = 0; it < n_items; it++) {
            MBARRIER_WAIT_PARITY(sb + MMAD_OFF(it & 1), (it >> 1) & 1);
            asm volatile("tcgen05.fence::after_thread_sync;" ::: "memory");
            const int t = (it < 3) ? (pair + it * NPAIRS) : t4;
            const int mi = t & 31, ni = t >> 5;
            const bool is_helper = (it == 3) && (pair >= NSPLIT);

            float* orow;
            float bw;
            if (is_helper) {
                orow = g_part + ((size_t)s34 * 256 + prow) * 512;
                bw = 0.0f;
            } else {
                orow = out + (size_t)(mi * 256 + prow) * N + ni * 512;
                bw = 1.0f;
            }
            const float* brow = bias + ni * 512;

#pragma unroll
            for (int cc = 0; cc < 256; cc += 16) {
                const int col = half * 256 + cc;
                uint32_t r[16];
                LDTM_X16(r, tmem + (uint32_t)col);
                asm volatile("tcgen05.wait::ld.sync.aligned;" ::: "memory");
                const float4* bp = reinterpret_cast<const float4*>(brow + col);
                float4* op = reinterpret_cast<float4*>(orow + col);
#pragma unroll
                for (int j = 0; j < 4; j++) {
                    float4 bv = bp[j];
                    float4 v;
                    v.x = __uint_as_float(r[4 * j + 0]) + bw * bv.x;
                    v.y = __uint_as_float(r[4 * j + 1]) + bw * bv.y;
                    v.z = __uint_as_float(r[4 * j + 2]) + bw * bv.z;
                    v.w = __uint_as_float(r[4 * j + 3]) + bw * bv.w;
                    op[j] = v;
                }
            }
            asm volatile("tcgen05.fence::before_thread_sync;" ::: "memory");
            if (elect_one()) {
                if (rank == 0) MBARRIER_ARRIVE_LOCAL(sb + EPI_OFF(it & 1));
                else           MBARRIER_ARRIVE_RANK0(sb + EPI_OFF(it & 1));
            }
        }
    }

    __syncthreads();
    CLUSTER_SYNC();
    if (wid == 8) {
        asm volatile("tcgen05.dealloc.cta_group::2.sync.aligned.b32 %0, %1;"
                     :: "r"(tmem), "r"((uint32_t)TMEM_COLS));
    }
    CLUSTER_SYNC();

#else
    // ======================= mma.sync tf32 fallback ========================
    // Full-K over all 256 tiles; also zero g_part so reduce_kernel is a no-op.
    for (int i = blockIdx.x * blockDim.x + threadIdx.x;
         i < NSPLIT * 256 * 512 / 4; i += gridDim.x * blockDim.x) {
        reinterpret_cast<float4*>(g_part)[i] = make_float4(0.f, 0.f, 0.f, 0.f);
    }
    const int wm = (wid & 1) * 64;
    const int wn = ((wid >> 1) & 3) * 64;
    const int g  = lid >> 2;
    const int t4l = lid & 3;
    const int KCH = K / BK;

    for (int t = pair; t < 256; t += NPAIRS) {
        const int mi = t & 31, ni = t >> 5;
        const int m0 = mi * 256 + rank * 128;
        const int n0b = ni * 512;
        const float* gA0 = x + (size_t)m0 * K;

        for (int h = 0; h < 2; h++) {
            const float* gB0 = g_wm + (size_t)(n0b + h * 256) * K;

            float acc[4][8][4];
#pragma unroll
            for (int i = 0; i < 4; i++)
#pragma unroll
                for (int j = 0; j < 8; j++)
#pragma unroll
                    for (int c = 0; c < 4; c++) acc[i][j][c] = 0.0f;

            if (tid < NLOAD) {
#pragma unroll
                for (int s = 0; s < 3; s++)
                    load_stage_fb(sb, s, gA0 + s * BK, gB0 + s * BK, K, tid);
            }

            for (int k = 0; k < KCH; k++) {
                if (tid < NLOAD) {
                    int pend = KCH - 1 - k; if (pend > 2) pend = 2;
                    if (pend <= 0)      asm volatile("cp.async.wait_group 0;" ::: "memory");
                    else if (pend == 1) asm volatile("cp.async.wait_group 1;" ::: "memory");
                    else                asm volatile("cp.async.wait_group 2;" ::: "memory");
                }
                __syncthreads();

                if (tid < NLOAD && k + 3 < KCH) {
                    const int c = k + 3;
                    load_stage_fb(sb, (k + 3) & 3, gA0 + (size_t)c * BK,
                                  gB0 + (size_t)c * BK, K, tid);
                }

                if (wid < 8) {
                    const uint32_t sa = sb + SMEM_STAGE0 + (k & 3) * FB_STAGE_BYTES;
                    const uint32_t sB = sa + FB_A_BYTES;
#pragma unroll
                    for (int k8 = 0; k8 < 4; k8++) {
                        const int kc = k8 * 8;
                        uint32_t a[4][4];
#pragma unroll
                        for (int mt = 0; mt < 4; mt++) {
                            const int r0 = wm + mt * 16 + g;
                            const int c0 = kc + t4l;
                            a[mt][0] = lds_u32(sa + SWZ((uint32_t)(r0 * 128 + c0 * 4)));
                            a[mt][1] = lds_u32(sa + SWZ((uint32_t)((r0 + 8) * 128 + c0 * 4)));
                            a[mt][2] = lds_u32(sa + SWZ((uint32_t)(r0 * 128 + (c0 + 4) * 4)));
                            a[mt][3] = lds_u32(sa + SWZ((uint32_t)((r0 + 8) * 128 + (c0 + 4) * 4)));
                        }
                        uint32_t b[8][2];
#pragma unroll
                        for (int nt = 0; nt < 8; nt++) {
                            const int n = wn + nt * 8 + g;
                            const int ck = kc + t4l;
                            b[nt][0] = lds_u32(sB + SWZ((uint32_t)(n * 128 + ck * 4)));
                            b[nt][1] = lds_u32(sB + SWZ((uint32_t)(n * 128 + (ck + 4) * 4)));
                        }
#pragma unroll
                        for (int mt = 0; mt < 4; mt++)
#pragma unroll
                            for (int nt = 0; nt < 8; nt++) {
                                asm volatile(
                                    "mma.sync.aligned.m16n8k8.row.col.f32.tf32.tf32.f32 "
                                    "{%0,%1,%2,%3}, {%4,%5,%6,%7}, {%8,%9}, {%0,%1,%2,%3};"
                                    : "+f"(acc[mt][nt][0]), "+f"(acc[mt][nt][1]),
                                      "+f"(acc[mt][nt][2]), "+f"(acc[mt][nt][3])
                                    : "r"(a[mt][0]), "r"(a[mt][1]), "r"(a[mt][2]), "r"(a[mt][3]),
                                      "r"(b[nt][0]), "r"(b[nt][1]));
                            }
                    }
                }
            }
            __syncthreads();

            if (wid < 8) {
#pragma unroll
                for (int mt = 0; mt < 4; mt++) {
                    const int row0 = m0 + wm + mt * 16 + g;
#pragma unroll
                    for (int nt = 0; nt < 8; nt++) {
                        const int col0 = n0b + h * 256 + wn + nt * 8 + t4l * 2;
                        const float2 bv = *reinterpret_cast<const float2*>(bias + col0);
                        float2 v0, v1;
                        v0.x = acc[mt][nt][0] + bv.x;
                        v0.y = acc[mt][nt][1] + bv.y;
                        v1.x = acc[mt][nt][2] + bv.x;
                        v1.y = acc[mt][nt][3] + bv.y;
                        *reinterpret_cast<float2*>(out + (size_t)row0 * N + col0) = v0;
                        *reinterpret_cast<float2*>(out + (size_t)(row0 + 8) * N + col0) = v1;
                    }
                }
            }
            __syncthreads();
        }
    }
#endif
}

// ---------------------------------------------------------------------------
// host: tensor map encode (dlopen'd driver API) + launch
// ---------------------------------------------------------------------------
typedef CUresult (*PFN_tmEncode)(
    CUtensorMap*, CUtensorMapDataType, cuuint32_t, void*,
    const cuuint64_t*, const cuuint64_t*, const cuuint32_t*, const cuuint32_t*,
    CUtensorMapInterleave, CUtensorMapSwizzle, CUtensorMapL2promotion,
    CUtensorMapFloatOOBfill);

static PFN_tmEncode get_encoder() {
    static PFN_tmEncode fn = nullptr;
    if (!fn) {
        void* h = dlopen("libcuda.so.1", RTLD_NOW | RTLD_GLOBAL);
        if (!h) h = dlopen("libcuda.so", RTLD_NOW | RTLD_GLOBAL);
        if (h) fn = (PFN_tmEncode)dlsym(h, "cuTensorMapEncodeTiled");
    }
    return fn;
}

static void encode_map(PFN_tmEncode enc, CUtensorMap* tm, void* base,
                       uint64_t rows, uint64_t cols_elems) {
    cuuint64_t dims[3]    = {cols_elems, rows, 1};
    cuuint64_t strides[2] = {cols_elems * 4, rows * cols_elems * 4};
    cuuint32_t box[3]     = {32, 128, 1};     // 32 f32 = 128 B (SW128 limit)
    cuuint32_t estr[3]    = {1, 1, 1};
    enc(tm, CU_TENSOR_MAP_DATA_TYPE_FLOAT32, 3, base, dims, strides, box, estr,
        CU_TENSOR_MAP_INTERLEAVE_NONE, CU_TENSOR_MAP_SWIZZLE_128B,
        CU_TENSOR_MAP_L2_PROMOTION_L2_128B, CU_TENSOR_MAP_FLOAT_OOB_FILL_NONE);
}

extern "C" void kernel_launch(void* const* d_in, const int* in_sizes, int n_in,
                              void* d_out, int out_size) {
    const float* x    = (const float*)d_in[0];
    const float* w    = (const float*)d_in[1];
    const float* bias = (const float*)d_in[2];
    const float* mask = (const float*)d_in[3];
    float* out = (float*)d_out;

    const int N = in_sizes[2];                  // 4096
    const int K = in_sizes[1] / N;              // 4096
    const int M = in_sizes[0] / K;              // 8192

    {
        int n4 = (N * K) / 4;
        prep_w_kernel<<<(n4 + 255) / 256, 256>>>((const float4*)w,
                                                 (const float4*)mask, n4);
    }

    static CUtensorMap tmx, tmw;
    PFN_tmEncode enc = get_encoder();
    void* wm_ptr = nullptr;
    cudaGetSymbolAddress(&wm_ptr, g_wm);
    if (enc) {
        encode_map(enc, &tmx, (void*)x, (uint64_t)M, (uint64_t)K);
        encode_map(enc, &tmw, wm_ptr,   (uint64_t)N, (uint64_t)K);
    }

    cudaFuncSetAttribute(masked_gemm_kernel,
                         cudaFuncAttributeMaxDynamicSharedMemorySize, SMEM_TOTAL);
    masked_gemm_kernel<<<148, THREADS, SMEM_TOTAL>>>(x, bias, out, M, N, K,
                                                     tmx, tmw);

    {
        const int total4 = NSPLIT * 256 * 512 / 4;
        reduce_kernel<<<(total4 + 255) / 256, 256>>>(out, N);
    }
}